// round 15
// baseline (speedup 1.0000x reference)
#include <cuda_runtime.h>
#include <math.h>
#include <stdio.h>

#define NSITE 131072              // 32*16*16*16
#define NS9   (NSITE * 9)         // 1179648

struct Lims { long ur, ui, wr, wi, ah, out; };

// Clamped load: index forced into [0, lim). Cannot fault on a buffer of >= lim
// elements; limits are the harness-reported element counts (verified by diag).
__device__ __forceinline__ float ldc(const float* __restrict__ p, long i, long lim) {
    long j = i < lim ? i : (lim - 1);
    if (j < 0) j = 0;
    return p[j];
}

__global__ void lge_real(const float* __restrict__ Ur, const float* __restrict__ Ui,
                         const float* __restrict__ Wr, const float* __restrict__ Wi,
                         const float* __restrict__ Ah, float* __restrict__ out,
                         const Lims lim)
{
    const int site = blockIdx.x * blockDim.x + threadIdx.x;
    if (site >= NSITE) return;
    const long s9 = (long)site * 9;

    // E accumulators, 4 mu: [0..2] diag imag, [3,4] E01(r,i), [5,6] E02, [7,8] E12
    float E[4][9];
    #pragma unroll
    for (int m = 0; m < 4; m++)
        #pragma unroll
        for (int k = 0; k < 9; k++) E[m][k] = 0.f;

    // ---- accumulate over 8 features; W read exactly once per site ----
    #pragma unroll
    for (int f = 0; f < 8; f++) {
        float wr[9], wi[9];
        const long b = (long)f * NS9 + s9;
        #pragma unroll
        for (int k = 0; k < 9; k++) {
            wr[k] = ldc(Wr, b + k, lim.wr);
            wi[k] = ldc(Wi, b + k, lim.wi);
        }
        const float tr  = wi[0] + wi[4] + wi[8];
        const float t23 = tr * (2.f / 3.f);
        const float d0 = 2.f * wi[0] - t23;
        const float d1 = 2.f * wi[4] - t23;
        const float d2 = 2.f * wi[8] - t23;
        const float a01r = wr[1] - wr[3], a01i = wi[1] + wi[3];
        const float a02r = wr[2] - wr[6], a02i = wi[2] + wi[6];
        const float a12r = wr[5] - wr[7], a12i = wi[5] + wi[7];
        #pragma unroll
        for (int m = 0; m < 4; m++) {
            const float g = ldc(Ah, m * 8 + f, lim.ah);   // uniform -> L1 broadcast
            E[m][0] += g * d0;   E[m][1] += g * d1;   E[m][2] += g * d2;
            E[m][3] += g * a01r; E[m][4] += g * a01i;
            E[m][5] += g * a02r; E[m][6] += g * a02i;
            E[m][7] += g * a12r; E[m][8] += g * a12i;
        }
    }

    // ---- per-mu: closed-form su(3) exponential, apply to U, store Re only ----
    #pragma unroll
    for (int m = 0; m < 4; m++) {
        // H = -iE : hermitian traceless
        const float h00 = E[m][0], h11 = E[m][1], h22 = E[m][2];
        const float h01r =  E[m][4], h01i = -E[m][3];
        const float h02r =  E[m][6], h02i = -E[m][5];
        const float h12r =  E[m][8], h12i = -E[m][7];

        // H^2 (hermitian)
        const float n01 = h01r * h01r + h01i * h01i;
        const float n02 = h02r * h02r + h02i * h02i;
        const float n12 = h12r * h12r + h12i * h12i;
        const float H2_00 = h00 * h00 + n01 + n02;
        const float H2_11 = h11 * h11 + n01 + n12;
        const float H2_22 = h22 * h22 + n02 + n12;
        const float H2_01r = (h00 + h11) * h01r + (h02r * h12r + h02i * h12i);
        const float H2_01i = (h00 + h11) * h01i + (h02i * h12r - h02r * h12i);
        const float H2_02r = (h00 + h22) * h02r + (h01r * h12r - h01i * h12i);
        const float H2_02i = (h00 + h22) * h02i + (h01r * h12i + h01i * h12r);
        const float H2_12r = (h11 + h22) * h12r + (h01r * h02r + h01i * h02i);
        const float H2_12i = (h11 + h22) * h12i + (h01r * h02i - h01i * h02r);

        const float c1 = 0.5f * (H2_00 + H2_11 + H2_22);
        const float c0 = (h00 * H2_00 + h11 * H2_11 + h22 * H2_22
                         + 2.f * (H2_01r * h01r + H2_01i * h01i
                                + H2_02r * h02r + H2_02i * h02i
                                + H2_12r * h12r + H2_12i * h12i)) * (1.f / 3.f);

        // Morningstar-Peardon: exp(iH) = f0 + f1 H + f2 H^2
        float f0r, f0i, f1r, f1i, f2r, f2i;
        if (c1 < 1e-9f) {
            f0r = 1.f; f0i = 0.f; f1r = 0.f; f1i = 1.f; f2r = -0.5f; f2i = 0.f;
        } else {
            const float c0a   = fabsf(c0);
            const float c13   = c1 * (1.f / 3.f);
            const float sq3   = sqrtf(c13);
            const float c0max = 2.f * c13 * sq3;
            const float x     = fminf(c0a / c0max, 1.f);
            const float th    = acosf(x) * (1.f / 3.f);
            float st, ct;  sincosf(th, &st, &ct);
            const float u  = sq3 * ct;
            const float w  = sqrtf(c1) * st;
            const float u2 = u * u, w2 = w * w;
            float sw, cw;  sincosf(w, &sw, &cw);
            const float xi0 = (w > 0.02f) ? (sw / w)
                                          : (1.f - w2 * (1.f / 6.f) * (1.f - w2 * 0.05f));
            float su, cu;  sincosf(u, &su, &cu);
            const float c2u = cu * cu - su * su;
            const float s2u = 2.f * cu * su;
            const float rden = 1.f / (9.f * u2 - w2);   // >= 2*c1 > 0 here
            float a, b;
            a = 8.f * u2 * cw;  b = 2.f * u * (3.f * u2 + w2) * xi0;
            const float g0r = (u2 - w2) * c2u + (cu * a + su * b);
            const float g0i = (u2 - w2) * s2u + (cu * b - su * a);
            a = 2.f * u * cw;   b = -(3.f * u2 - w2) * xi0;
            const float g1r = 2.f * u * c2u - (cu * a + su * b);
            const float g1i = 2.f * u * s2u - (cu * b - su * a);
            a = cw;             b = 3.f * u * xi0;
            const float g2r = c2u - (cu * a + su * b);
            const float g2i = s2u - (cu * b - su * a);
            f0r = g0r * rden; f0i = g0i * rden;
            f1r = g1r * rden; f1i = g1i * rden;
            f2r = g2r * rden; f2i = g2i * rden;
            if (c0 < 0.f) {    // f_j(-c0) = (-1)^j conj(f_j(c0))
                f0i = -f0i;  f1r = -f1r;  f2i = -f2i;
            }
        }

        // Q = f0 I + f1 H + f2 H^2
        float qr[9], qi[9];
        qr[0] = f0r + f1r * h00 + f2r * H2_00;  qi[0] = f0i + f1i * h00 + f2i * H2_00;
        qr[4] = f0r + f1r * h11 + f2r * H2_11;  qi[4] = f0i + f1i * h11 + f2i * H2_11;
        qr[8] = f0r + f1r * h22 + f2r * H2_22;  qi[8] = f0i + f1i * h22 + f2i * H2_22;
        qr[1] = f1r * h01r - f1i * h01i + f2r * H2_01r - f2i * H2_01i;
        qi[1] = f1r * h01i + f1i * h01r + f2r * H2_01i + f2i * H2_01r;
        qr[2] = f1r * h02r - f1i * h02i + f2r * H2_02r - f2i * H2_02i;
        qi[2] = f1r * h02i + f1i * h02r + f2r * H2_02i + f2i * H2_02r;
        qr[5] = f1r * h12r - f1i * h12i + f2r * H2_12r - f2i * H2_12i;
        qi[5] = f1r * h12i + f1i * h12r + f2r * H2_12i + f2i * H2_12r;
        qr[3] = f1r * h01r + f1i * h01i + f2r * H2_01r + f2i * H2_01i;
        qi[3] = -f1r * h01i + f1i * h01r - f2r * H2_01i + f2i * H2_01r;
        qr[6] = f1r * h02r + f1i * h02i + f2r * H2_02r + f2i * H2_02i;
        qi[6] = -f1r * h02i + f1i * h02r - f2r * H2_02i + f2i * H2_02r;
        qr[7] = f1r * h12r + f1i * h12i + f2r * H2_12r + f2i * H2_12i;
        qi[7] = -f1r * h12i + f1i * h12r - f2r * H2_12i + f2i * H2_12r;

        // load U[mu][site], multiply, store ONLY the real part.
        // Output buffer holds out_size=4*NS9 float32 elements (diag-proven);
        // the test's reference was complex64 cast to float32 -> real part.
        const long ub = (long)m * NS9 + s9;
        float urv[9], uiv[9];
        #pragma unroll
        for (int k = 0; k < 9; k++) {
            urv[k] = ldc(Ur, ub + k, lim.ur);
            uiv[k] = ldc(Ui, ub + k, lim.ui);
        }
        #pragma unroll
        for (int a3 = 0; a3 < 3; a3++) {
            #pragma unroll
            for (int b3 = 0; b3 < 3; b3++) {
                float orr = 0.f;
                #pragma unroll
                for (int c = 0; c < 3; c++) {
                    const float q_r = qr[a3 * 3 + c], q_i = qi[a3 * 3 + c];
                    orr += q_r * urv[c * 3 + b3] - q_i * uiv[c * 3 + b3];
                }
                const long oidx = ub + a3 * 3 + b3;     // float32 slot, NO x2
                if (oidx < lim.out) out[oidx] = orr;
            }
        }
    }
}

extern "C" void kernel_launch(void* const* d_in, const int* in_sizes, int n_in,
                              void* d_out, int out_size)
{
    // diagnostics (kept: cheap, and self-explains any residual failure)
    fprintf(stderr, "[diag] n_in=%d out_size=%d d_out=%p\n", n_in, out_size, d_out);
    for (int i = 0; i < n_in; i++)
        fprintf(stderr, "[diag] in[%d] size=%d ptr=%p\n", i, in_sizes[i], d_in[i]);
    fflush(stderr);

    // Positional binding — diag-verified: 0:U_re 1:U_im 2:W_re 3:W_im 4:ah
    const float* Ur = (const float*)d_in[0];
    const float* Ui = (const float*)((n_in > 1) ? d_in[1] : d_in[0]);
    const float* Wr = (const float*)((n_in > 2) ? d_in[2] : d_in[0]);
    const float* Wi = (const float*)((n_in > 3) ? d_in[3] : d_in[0]);
    const float* Ah = (const float*)((n_in > 4) ? d_in[4] : d_in[0]);

    Lims lim;
    lim.ur = (long)in_sizes[0];
    lim.ui = (long)((n_in > 1) ? in_sizes[1] : in_sizes[0]);
    lim.wr = (long)((n_in > 2) ? in_sizes[2] : in_sizes[0]);
    lim.wi = (long)((n_in > 3) ? in_sizes[3] : in_sizes[0]);
    lim.ah = (long)((n_in > 4) ? in_sizes[4] : in_sizes[0]);
    if (lim.ur < 1) lim.ur = 1;
    if (lim.ui < 1) lim.ui = 1;
    if (lim.wr < 1) lim.wr = 1;
    if (lim.wi < 1) lim.wi = 1;
    if (lim.ah < 1) lim.ah = 1;

    // Output: exactly out_size float32 slots. NO promotion — the seven faults
    // proved the allocation is out_size * 4 bytes.
    lim.out = (long)out_size;
    if (lim.out < 0) lim.out = 0;

    const int threads = 256;
    const int blocks  = (NSITE + threads - 1) / threads;   // 512
    lge_real<<<blocks, threads>>>(Ur, Ui, Wr, Wi, Ah, (float*)d_out, lim);
}

// round 16
// speedup vs baseline: 1.1011x; 1.1011x over previous
#include <cuda_runtime.h>
#include <math.h>

#define NSITE   131072            // 32*16*16*16
#define NS9     (NSITE * 9)       // 1179648
#define SPB     64                // sites per block
#define THREADS 256
#define CHUNK   (SPB * 9)         // 576 floats per plane-chunk per block
#define CH4     (CHUNK / 4)       // 144 float4 per plane-chunk

__global__ __launch_bounds__(THREADS)
void lge_exp_kernel(const float4* __restrict__ U_re, const float4* __restrict__ U_im,
                    const float4* __restrict__ W_re, const float4* __restrict__ W_im,
                    const float* __restrict__ ah,    float* __restrict__ out)
{
    // s_w: stages 4 features (re+im): 8 * 576 floats = 18.4 KB
    //      reused as output staging: 4 mu * 576 floats (real only) = 9.2 KB
    __shared__ float s_w[8 * CHUNK];
    __shared__ float s_u[8 * CHUNK];   // 4 mu (re+im)

    const int tid = threadIdx.x;
    const int mu  = tid >> 6;      // 0..3
    const int sl  = tid & 63;      // local site
    const int blk = blockIdx.x;
    const long b4 = (long)blk * CH4;       // float4 offset inside each plane
    const long NS9_4 = NS9 / 4;

    float4* s_u4 = (float4*)s_u;
    float4* s_w4 = (float4*)s_w;

    // ---- stage U for all 4 mu (coalesced float4): 8 planes x 144 f4 ----
    for (int t = tid; t < 8 * CH4; t += THREADS) {
        const int plane = t / CH4;         // 0..7 : (mu, re/im)
        const int off   = t - plane * CH4;
        const int m     = plane >> 1;
        const float4 v  = (plane & 1)
            ? U_im[(long)m * NS9_4 + b4 + off]
            : U_re[(long)m * NS9_4 + b4 + off];
        s_u4[plane * CH4 + off] = v;
    }

    // ---- per-thread weights (uniform within warp -> L1 broadcast) ----
    float wgt[8];
    #pragma unroll
    for (int i = 0; i < 8; i++) wgt[i] = __ldg(&ah[mu * 8 + i]);

    // E anti-hermitian traceless: [0..2] diag imag, then E01, E02, E12 (r,i)
    float Ed0 = 0.f, Ed1 = 0.f, Ed2 = 0.f;
    float E01r = 0.f, E01i = 0.f, E02r = 0.f, E02i = 0.f, E12r = 0.f, E12i = 0.f;

    // ---- accumulate over 8 features, staged 4 at a time ----
    for (int g = 0; g < 2; g++) {
        __syncthreads();
        // 8 planes (4 feats x re/im) x 144 f4
        for (int t = tid; t < 8 * CH4; t += THREADS) {
            const int plane = t / CH4;
            const int off   = t - plane * CH4;
            const int f     = plane >> 1;
            const int feat  = g * 4 + f;
            const float4 v  = (plane & 1)
                ? W_im[(long)feat * NS9_4 + b4 + off]
                : W_re[(long)feat * NS9_4 + b4 + off];
            s_w4[plane * CH4 + off] = v;
        }
        __syncthreads();
        #pragma unroll
        for (int f = 0; f < 4; f++) {
            const float* wr = &s_w[(2 * f + 0) * CHUNK + sl * 9]; // stride 9: conflict-free
            const float* wi = &s_w[(2 * f + 1) * CHUNK + sl * 9];
            const float g0 = wgt[g * 4 + f];
            const float s  = wi[0] + wi[4] + wi[8];
            const float t23 = s * (2.f / 3.f);
            Ed0 += g0 * (2.f * wi[0] - t23);
            Ed1 += g0 * (2.f * wi[4] - t23);
            Ed2 += g0 * (2.f * wi[8] - t23);
            E01r += g0 * (wr[1] - wr[3]);  E01i += g0 * (wi[1] + wi[3]);
            E02r += g0 * (wr[2] - wr[6]);  E02i += g0 * (wi[2] + wi[6]);
            E12r += g0 * (wr[5] - wr[7]);  E12i += g0 * (wi[5] + wi[7]);
        }
    }

    // ---- H = -iE : hermitian traceless ----
    const float h00 = Ed0, h11 = Ed1, h22 = Ed2;
    const float h01r = E01i, h01i = -E01r;
    const float h02r = E02i, h02i = -E02r;
    const float h12r = E12i, h12i = -E12r;

    // ---- H^2 (hermitian) ----
    const float n01 = h01r * h01r + h01i * h01i;
    const float n02 = h02r * h02r + h02i * h02i;
    const float n12 = h12r * h12r + h12i * h12i;
    const float H2_00 = h00 * h00 + n01 + n02;
    const float H2_11 = h11 * h11 + n01 + n12;
    const float H2_22 = h22 * h22 + n02 + n12;
    const float H2_01r = (h00 + h11) * h01r + (h02r * h12r + h02i * h12i);
    const float H2_01i = (h00 + h11) * h01i + (h02i * h12r - h02r * h12i);
    const float H2_02r = (h00 + h22) * h02r + (h01r * h12r - h01i * h12i);
    const float H2_02i = (h00 + h22) * h02i + (h01r * h12i + h01i * h12r);
    const float H2_12r = (h11 + h22) * h12r + (h01r * h02r + h01i * h02i);
    const float H2_12i = (h11 + h22) * h12i + (h01r * h02i - h01i * h02r);

    const float c1 = 0.5f * (H2_00 + H2_11 + H2_22);
    const float c0 = (h00 * H2_00 + h11 * H2_11 + h22 * H2_22
                     + 2.f * (H2_01r * h01r + H2_01i * h01i
                            + H2_02r * h02r + H2_02i * h02i
                            + H2_12r * h12r + H2_12i * h12i)) * (1.f / 3.f);

    // ---- Morningstar-Peardon: exp(iH) = f0 + f1 H + f2 H^2 ----
    float f0r, f0i, f1r, f1i, f2r, f2i;
    if (c1 < 1e-9f) {
        f0r = 1.f; f0i = 0.f; f1r = 0.f; f1i = 1.f; f2r = -0.5f; f2i = 0.f;
    } else {
        const float c0a   = fabsf(c0);
        const float c13   = c1 * (1.f / 3.f);
        const float sq3   = sqrtf(c13);
        const float c0max = 2.f * c13 * sq3;
        const float x     = fminf(c0a / c0max, 1.f);
        const float th    = acosf(x) * (1.f / 3.f);
        float st, ct;  sincosf(th, &st, &ct);
        const float u  = sq3 * ct;
        const float w  = sqrtf(c1) * st;
        const float u2 = u * u, w2 = w * w;
        float sw, cw;  sincosf(w, &sw, &cw);
        const float xi0 = (w > 0.02f) ? (sw / w)
                                      : (1.f - w2 * (1.f / 6.f) * (1.f - w2 * 0.05f));
        float su, cu;  sincosf(u, &su, &cu);
        const float c2u = cu * cu - su * su;
        const float s2u = 2.f * cu * su;
        const float rden = 1.f / (9.f * u2 - w2);  // >= 2*c1 > 0 on this branch
        float a, b;
        a = 8.f * u2 * cw;  b = 2.f * u * (3.f * u2 + w2) * xi0;
        const float g0r = (u2 - w2) * c2u + (cu * a + su * b);
        const float g0i = (u2 - w2) * s2u + (cu * b - su * a);
        a = 2.f * u * cw;   b = -(3.f * u2 - w2) * xi0;
        const float g1r = 2.f * u * c2u - (cu * a + su * b);
        const float g1i = 2.f * u * s2u - (cu * b - su * a);
        a = cw;             b = 3.f * u * xi0;
        const float g2r = c2u - (cu * a + su * b);
        const float g2i = s2u - (cu * b - su * a);
        f0r = g0r * rden; f0i = g0i * rden;
        f1r = g1r * rden; f1i = g1i * rden;
        f2r = g2r * rden; f2i = g2i * rden;
        if (c0 < 0.f) {     // f_j(-c0) = (-1)^j conj(f_j(c0))
            f0i = -f0i;  f1r = -f1r;  f2i = -f2i;
        }
    }

    // ---- Q = f0 I + f1 H + f2 H^2 (full complex) ----
    float qr[9], qi[9];
    qr[0] = f0r + f1r * h00 + f2r * H2_00;  qi[0] = f0i + f1i * h00 + f2i * H2_00;
    qr[4] = f0r + f1r * h11 + f2r * H2_11;  qi[4] = f0i + f1i * h11 + f2i * H2_11;
    qr[8] = f0r + f1r * h22 + f2r * H2_22;  qi[8] = f0i + f1i * h22 + f2i * H2_22;
    qr[1] = f1r * h01r - f1i * h01i + f2r * H2_01r - f2i * H2_01i;
    qi[1] = f1r * h01i + f1i * h01r + f2r * H2_01i + f2i * H2_01r;
    qr[2] = f1r * h02r - f1i * h02i + f2r * H2_02r - f2i * H2_02i;
    qi[2] = f1r * h02i + f1i * h02r + f2r * H2_02i + f2i * H2_02r;
    qr[5] = f1r * h12r - f1i * h12i + f2r * H2_12r - f2i * H2_12i;
    qi[5] = f1r * h12i + f1i * h12r + f2r * H2_12i + f2i * H2_12r;
    qr[3] = f1r * h01r + f1i * h01i + f2r * H2_01r + f2i * H2_01i;
    qi[3] = -f1r * h01i + f1i * h01r - f2r * H2_01i + f2i * H2_01r;
    qr[6] = f1r * h02r + f1i * h02i + f2r * H2_02r + f2i * H2_02i;
    qi[6] = -f1r * h02i + f1i * h02r - f2r * H2_02i + f2i * H2_02r;
    qr[7] = f1r * h12r + f1i * h12i + f2r * H2_12r + f2i * H2_12i;
    qi[7] = -f1r * h12i + f1i * h12r - f2r * H2_12i + f2i * H2_12r;

    // ---- out = Re(Q @ U), staged in s_w (reused), coalesced store ----
    __syncthreads();   // all s_w compute reads done before reuse

    const float* ur = &s_u[(2 * mu + 0) * CHUNK + sl * 9];
    const float* ui = &s_u[(2 * mu + 1) * CHUNK + sl * 9];
    float* os = &s_w[mu * CHUNK + sl * 9];

    #pragma unroll
    for (int a3 = 0; a3 < 3; a3++) {
        #pragma unroll
        for (int b3 = 0; b3 < 3; b3++) {
            float orr = 0.f;
            #pragma unroll
            for (int c = 0; c < 3; c++) {
                orr += qr[a3 * 3 + c] * ur[c * 3 + b3]
                     - qi[a3 * 3 + c] * ui[c * 3 + b3];
            }
            os[a3 * 3 + b3] = orr;
        }
    }

    __syncthreads();

    // gmem out: [mu][site][3][3] float32 (real part), coalesced float4
    float4* out4 = (float4*)out;
    for (int t = tid; t < 4 * CH4; t += THREADS) {
        const int m   = t / CH4;
        const int off = t - m * CH4;
        out4[(long)m * NS9_4 + b4 + off] = s_w4[m * CH4 + off];
    }
}

extern "C" void kernel_launch(void* const* d_in, const int* in_sizes, int n_in,
                              void* d_out, int out_size)
{
    // Diag-proven layout: 0:U_re(4*NS9) 1:U_im 2:W_re(8*NS9) 3:W_im 4:ah(32),
    // all float32 device buffers; out = 4*NS9 float32 (real part).
    const float4* Ur = (const float4*)d_in[0];
    const float4* Ui = (const float4*)d_in[1];
    const float4* Wr = (const float4*)d_in[2];
    const float4* Wi = (const float4*)d_in[3];
    const float*  Ah = (const float*)d_in[4];

    dim3 grid(NSITE / SPB);   // 2048
    dim3 block(THREADS);
    lge_exp_kernel<<<grid, block>>>(Ur, Ui, Wr, Wi, Ah, (float*)d_out);
}